// round 4
// baseline (speedup 1.0000x reference)
#include <cuda_runtime.h>
#include <math.h>

#define A_DIM 20
#define L_DIM 512
#define CH 8
#define B_DIM 1024
#define TPB 128   // 4 warps; warp w owns amino acids 5w..5w+4

__device__ float g_W[CH * L_DIM];   // composed linear map: out[c] = sum_l W[c,l] h[l]

// ---------------------------------------------------------------------------
// f32x2 packed helpers (Blackwell FFMA2 path)
// ---------------------------------------------------------------------------
__device__ __forceinline__ unsigned long long pack2(float lo, float hi) {
    unsigned long long r;
    asm("mov.b64 %0, {%1, %2};" : "=l"(r) : "f"(lo), "f"(hi));
    return r;
}
__device__ __forceinline__ void unpack2(unsigned long long v, float& lo, float& hi) {
    asm("mov.b64 {%0, %1}, %2;" : "=f"(lo), "=f"(hi) : "l"(v));
}
__device__ __forceinline__ void ffma2(unsigned long long& d, unsigned long long a,
                                      unsigned long long b) {
    asm("fma.rn.f32x2 %0, %1, %2, %0;" : "+l"(d) : "l"(a), "l"(b));
}

// ---------------------------------------------------------------------------
// Kernel 1: W via adjoint composition. One block per output channel oc.
// Pull delta at the (8,1) output backward through pool^T / conv^T chain.
// Forward: h0(1,512) -conv w0-> pool -> (8,256) -ws[0]-> pool ... ws[7] -> (8,1)
// ---------------------------------------------------------------------------
__global__ __launch_bounds__(256) void build_w_bwd(const float* __restrict__ w0,
                                                   const float* __restrict__ ws) {
    __shared__ float GA[CH][256];
    __shared__ float GB[CH][256];
    __shared__ float sws[8 * CH * CH * 3];
    __shared__ float sw0[CH * 3];
    int tid = threadIdx.x, oc = blockIdx.x;

    for (int i = tid; i < 8 * CH * CH * 3; i += 256) sws[i] = ws[i];
    if (tid < CH * 3) sw0[tid] = w0[tid];
    if (tid < CH) GA[tid][0] = (tid == oc) ? 1.f : 0.f;
    __syncthreads();

    float (*cur)[256] = GA, (*nxt)[256] = GB;
    // backward through conv ws[j] (+ preceding pool), j = 7..0
    for (int j = 7; j >= 0; j--) {
        int L2h = 256 >> j;  // length at conv ws[j]
        const float* w = &sws[j * CH * CH * 3];
        for (int e = tid; e < CH * L2h; e += 256) {
            int ci = e / L2h, q = e % L2h;
            float acc = 0.f;
            #pragma unroll
            for (int co = 0; co < CH; co++) {
                const float* wc = w + (co * CH + ci) * 3;
                #pragma unroll
                for (int t = 0; t < 3; t++) {
                    int p = q + 1 - t;             // z position feeding y[ci][q]
                    if (p >= 0 && p < L2h) acc += wc[t] * 0.5f * cur[co][p >> 1];
                }
            }
            nxt[ci][q] = acc;
        }
        __syncthreads();
        float (*tmp)[256] = cur; cur = nxt; nxt = tmp;
    }
    // backward through pool0 + conv0 (1 -> 8): produce W[oc][q], q in [0,512)
    for (int q = tid; q < 512; q += 256) {
        float acc = 0.f;
        #pragma unroll
        for (int co = 0; co < CH; co++) {
            #pragma unroll
            for (int t = 0; t < 3; t++) {
                int p = q + 1 - t;
                if (p >= 0 && p < 512) acc += sw0[co * 3 + t] * 0.5f * cur[co][p >> 1];
            }
        }
        g_W[oc * L_DIM + q] = acc;
    }
}

// ---------------------------------------------------------------------------
// Kernel 2: main. One block per batch element.
//   A: decode one-hot -> sav[l] in {0..19, 20=masked}
//   B: per-l exclusive class masks c1/c2/c3 (bit a set => row value v1/v2/v3)
//   C: warp w, a in {5w..5w+4}: h = classSel + Vp[a][sav]; packed FFMA2 dots
//   D: butterfly reduce, float4 stores
// ---------------------------------------------------------------------------
__global__ __launch_bounds__(TPB) void main_kernel(const float* __restrict__ x,
                                                   const float* __restrict__ lpm,
                                                   const float* __restrict__ pm,
                                                   const float* __restrict__ stdv,
                                                   float* __restrict__ out) {
    __shared__ unsigned long long Wp[4 * L_DIM];  // pair j: channels (2j,2j+1), [j*512+l]
    __shared__ float Vt[A_DIM * 21];              // Vt[a*21+s] = V[s][a] + (s==a)
    __shared__ unsigned sc1[L_DIM], sc2[L_DIM], sc3[L_DIM];
    __shared__ int sav[L_DIM];

    int tid = threadIdx.x, b = blockIdx.x;

    // W channel pairs (g_W is L2-resident, 16KB)
    for (int t = tid; t < 4 * L_DIM; t += TPB) {
        int j = t >> 9, l = t & 511;
        Wp[t] = pack2(g_W[(2 * j) * L_DIM + l], g_W[(2 * j + 1) * L_DIM + l]);
    }
    // Vt with one-hot folded in
    for (int i = tid; i < A_DIM * 21; i += TPB) {
        int a = i / 21, s = i % 21;
        float v = (s == a) ? 1.f : 0.f;
        if (s < A_DIM) {
            if (a > s && a <= A_DIM - 2)
                v += fminf(fmaxf(lpm[s * A_DIM + a], 0.001f), 1.f) * pm[s * A_DIM + a];
            if (a < s)
                v += fminf(fmaxf(lpm[a * A_DIM + s], 0.001f), 1.f) * pm[a * A_DIM + s];
        }
        Vt[i] = v;
    }

    // Phase A: decode one-hot rows (80B each)
    const float* xb = x + (size_t)b * (L_DIM * A_DIM);
    #pragma unroll
    for (int r = 0; r < 4; r++) {
        int l = tid + r * TPB;
        const float4* p = (const float4*)(xb + l * A_DIM);
        int aa = 20;
        #pragma unroll
        for (int jj = 0; jj < 5; jj++) {
            float4 q = p[jj];
            if (q.x != 0.f) aa = 4 * jj + 0;
            if (q.y != 0.f) aa = 4 * jj + 1;
            if (q.z != 0.f) aa = 4 * jj + 2;
            if (q.w != 0.f) aa = 4 * jj + 3;
        }
        sav[l] = aa;
    }
    __syncthreads();

    // Phase B: exclusive class masks over a (bit 20 = masked, never tested)
    #pragma unroll
    for (int r = 0; r < 4; r++) {
        int l = tid + r * TPB;
        unsigned c1, c2, c3;
        if (l == 0) {
            c3 = (1u << sav[0]) | (1u << sav[1]) | (1u << sav[2]) | (1u << sav[3]);
            c2 = 0u; c1 = 0u;
        } else if (l == L_DIM - 1) {
            c3 = (1u << sav[511]) | (1u << sav[510]) | (1u << sav[509]) | (1u << sav[508]);
            c2 = 0u; c1 = 0u;
        } else {
            unsigned m1 = (1u << sav[l - 1]) | (1u << sav[l + 1]);
            unsigned m2 = ((l >= 2) ? (1u << sav[l - 2]) : 0u) |
                          ((l <= 509) ? (1u << sav[l + 2]) : 0u);
            unsigned m3 = ((l >= 3) ? (1u << sav[l - 3]) : 0u) |
                          ((l <= 508) ? (1u << sav[l + 3]) : 0u);
            c3 = m3;
            c2 = m2 & ~m3;
            c1 = m1 & ~(m2 | m3);
        }
        sc1[l] = c1; sc2[l] = c2; sc3[l] = c3;
    }
    __syncthreads();

    float s0 = stdv[0];
    float inv = 1.f / (2.f * s0 * s0);
    float v1 = expf(-1.f * inv), v2 = expf(-4.f * inv), v3 = expf(-9.f * inv);

    int warp = tid >> 5, lane = tid & 31;
    int abase = warp * 5;

    unsigned long long acc[5][4];
    #pragma unroll
    for (int aa = 0; aa < 5; aa++)
        #pragma unroll
        for (int j = 0; j < 4; j++) acc[aa][j] = 0ull;

    unsigned abit[5]; int vb[5];
    #pragma unroll
    for (int aa = 0; aa < 5; aa++) {
        abit[aa] = 1u << (abase + aa);
        vb[aa] = (abase + aa) * 21;
    }

    // Phase C: barrier-free packed accumulation
    #pragma unroll 2
    for (int i = 0; i < 16; i++) {
        int l = lane + 32 * i;
        unsigned c1 = sc1[l], c2 = sc2[l], c3 = sc3[l];
        int s = sav[l];
        unsigned long long w0p = Wp[l];
        unsigned long long w1p = Wp[512 + l];
        unsigned long long w2p = Wp[1024 + l];
        unsigned long long w3p = Wp[1536 + l];
        #pragma unroll
        for (int aa = 0; aa < 5; aa++) {
            float rv = (c3 & abit[aa]) ? v3
                     : (c2 & abit[aa]) ? v2
                     : (c1 & abit[aa]) ? v1 : 0.f;
            float h = rv + Vt[vb[aa] + s];
            unsigned long long hh = pack2(h, h);
            ffma2(acc[aa][0], w0p, hh);
            ffma2(acc[aa][1], w1p, hh);
            ffma2(acc[aa][2], w2p, hh);
            ffma2(acc[aa][3], w3p, hh);
        }
    }

    // Phase D: reduce + store
    #pragma unroll
    for (int aa = 0; aa < 5; aa++) {
        float v[8];
        #pragma unroll
        for (int j = 0; j < 4; j++) unpack2(acc[aa][j], v[2 * j], v[2 * j + 1]);
        #pragma unroll
        for (int c = 0; c < 8; c++) {
            #pragma unroll
            for (int off = 16; off; off >>= 1)
                v[c] += __shfl_xor_sync(0xFFFFFFFFu, v[c], off);
        }
        if (lane == 0) {
            float4* o = (float4*)(out + (size_t)b * (A_DIM * CH) + (abase + aa) * CH);
            o[0] = make_float4(v[0], v[1], v[2], v[3]);
            o[1] = make_float4(v[4], v[5], v[6], v[7]);
        }
    }
}

// ---------------------------------------------------------------------------
// Inputs (metadata order): x, masks(unused), lpm, pm, std, w0, ws
// Output: float32 (B, A, CH) = (1024, 20, 8)
// ---------------------------------------------------------------------------
extern "C" void kernel_launch(void* const* d_in, const int* in_sizes, int n_in,
                              void* d_out, int out_size) {
    const float* x    = (const float*)d_in[0];
    const float* lpm  = (const float*)d_in[2];
    const float* pm   = (const float*)d_in[3];
    const float* stdv = (const float*)d_in[4];
    const float* w0   = (const float*)d_in[5];
    const float* ws   = (const float*)d_in[6];
    float* out = (float*)d_out;

    build_w_bwd<<<CH, 256>>>(w0, ws);
    main_kernel<<<B_DIM, TPB>>>(x, lpm, pm, stdv, out);
}

// round 5
// speedup vs baseline: 1.0656x; 1.0656x over previous
#include <cuda_runtime.h>
#include <math.h>

#define A_DIM 20
#define L_DIM 512
#define CH 8
#define B_DIM 1024
#define TPB 128   // 4 warps; warp w owns amino acids 5w..5w+4

__device__ float g_W[CH * L_DIM];   // composed linear map: out[c] = sum_l W[c,l] h[l]

// ---------------------------------------------------------------------------
// f32x2 packed helpers (Blackwell FFMA2/FADD2 path)
// ---------------------------------------------------------------------------
__device__ __forceinline__ unsigned long long pack2(float lo, float hi) {
    unsigned long long r;
    asm("mov.b64 %0, {%1, %2};" : "=l"(r) : "f"(lo), "f"(hi));
    return r;
}
__device__ __forceinline__ void unpack2(unsigned long long v, float& lo, float& hi) {
    asm("mov.b64 {%0, %1}, %2;" : "=f"(lo), "=f"(hi) : "l"(v));
}
__device__ __forceinline__ void ffma2(unsigned long long& d, unsigned long long a,
                                      unsigned long long b) {
    asm("fma.rn.f32x2 %0, %1, %2, %0;" : "+l"(d) : "l"(a), "l"(b));
}
__device__ __forceinline__ unsigned long long add2(unsigned long long a,
                                                   unsigned long long b) {
    unsigned long long r;
    asm("add.rn.f32x2 %0, %1, %2;" : "=l"(r) : "l"(a), "l"(b));
    return r;
}
__device__ __forceinline__ unsigned long long shfl64(unsigned long long v, int off) {
    float lo, hi;
    unpack2(v, lo, hi);
    lo = __shfl_xor_sync(0xFFFFFFFFu, lo, off);
    hi = __shfl_xor_sync(0xFFFFFFFFu, hi, off);
    return pack2(lo, hi);
}

// ---------------------------------------------------------------------------
// Kernel 1: W via adjoint composition. One block per output channel oc.
// ---------------------------------------------------------------------------
__global__ __launch_bounds__(256) void build_w_bwd(const float* __restrict__ w0,
                                                   const float* __restrict__ ws) {
    __shared__ float GA[CH][256];
    __shared__ float GB[CH][256];
    __shared__ float sws[8 * CH * CH * 3];
    __shared__ float sw0[CH * 3];
    int tid = threadIdx.x, oc = blockIdx.x;

    for (int i = tid; i < 8 * CH * CH * 3; i += 256) sws[i] = ws[i];
    if (tid < CH * 3) sw0[tid] = w0[tid];
    if (tid < CH) GA[tid][0] = (tid == oc) ? 1.f : 0.f;
    __syncthreads();

    float (*cur)[256] = GA, (*nxt)[256] = GB;
    for (int j = 7; j >= 0; j--) {
        int L2h = 256 >> j;
        const float* w = &sws[j * CH * CH * 3];
        for (int e = tid; e < CH * L2h; e += 256) {
            int ci = e / L2h, q = e % L2h;
            float acc = 0.f;
            #pragma unroll
            for (int co = 0; co < CH; co++) {
                const float* wc = w + (co * CH + ci) * 3;
                #pragma unroll
                for (int t = 0; t < 3; t++) {
                    int p = q + 1 - t;
                    if (p >= 0 && p < L2h) acc += wc[t] * 0.5f * cur[co][p >> 1];
                }
            }
            nxt[ci][q] = acc;
        }
        __syncthreads();
        float (*tmp)[256] = cur; cur = nxt; nxt = tmp;
    }
    for (int q = tid; q < 512; q += 256) {
        float acc = 0.f;
        #pragma unroll
        for (int co = 0; co < CH; co++) {
            #pragma unroll
            for (int t = 0; t < 3; t++) {
                int p = q + 1 - t;
                if (p >= 0 && p < 512) acc += sw0[co * 3 + t] * 0.5f * cur[co][p >> 1];
            }
        }
        g_W[oc * L_DIM + q] = acc;
    }
}

// ---------------------------------------------------------------------------
// Kernel 2: main. One block per batch element.
// ---------------------------------------------------------------------------
__global__ __launch_bounds__(TPB) void main_kernel(const float* __restrict__ x,
                                                   const float* __restrict__ lpm,
                                                   const float* __restrict__ pm,
                                                   const float* __restrict__ stdv,
                                                   float* __restrict__ out) {
    __shared__ unsigned long long Wp[4 * L_DIM];   // channel pairs
    __shared__ float Vt[A_DIM * 21];               // Vt[a*21+s] = V[s][a] + (s==a)
    __shared__ unsigned long long scm[L_DIM];      // (c2 << 32) | c3
    __shared__ unsigned sc1s[L_DIM];               // c1 | (s << 24)
    __shared__ int sav[L_DIM];
    __shared__ int sWmax[4];

    int tid = threadIdx.x, b = blockIdx.x;
    int warp = tid >> 5, lane = tid & 31;

    // --- setup: W pairs + Vt ---
    for (int t = tid; t < 4 * L_DIM; t += TPB) {
        int j = t >> 9, l = t & 511;
        Wp[t] = pack2(g_W[(2 * j) * L_DIM + l], g_W[(2 * j + 1) * L_DIM + l]);
    }
    for (int i = tid; i < A_DIM * 21; i += TPB) {
        int a = i / 21, s = i % 21;
        float v = (s == a) ? 1.f : 0.f;
        if (s < A_DIM) {
            if (a > s && a <= A_DIM - 2)
                v += fminf(fmaxf(lpm[s * A_DIM + a], 0.001f), 1.f) * pm[s * A_DIM + a];
            if (a < s)
                v += fminf(fmaxf(lpm[a * A_DIM + s], 0.001f), 1.f) * pm[a * A_DIM + s];
        }
        Vt[i] = v;
    }

    // --- Phase A: decode one-hot via weighted-sum FMA trick ---
    const float* xb = x + (size_t)b * (L_DIM * A_DIM);
    int lmax = -1;
    #pragma unroll
    for (int r = 0; r < 4; r++) {
        int l = tid + r * TPB;
        const float4* p = (const float4*)(xb + l * A_DIM);
        float4 q0 = p[0], q1 = p[1], q2 = p[2], q3 = p[3], q4 = p[4];
        float a0 = fmaf(q0.x, 1.f, fmaf(q0.y, 2.f, fmaf(q0.z, 3.f, q0.w * 4.f)));
        float a1 = fmaf(q1.x, 5.f, fmaf(q1.y, 6.f, fmaf(q1.z, 7.f, q1.w * 8.f)));
        float a2 = fmaf(q2.x, 9.f, fmaf(q2.y, 10.f, fmaf(q2.z, 11.f, q2.w * 12.f)));
        float a3 = fmaf(q3.x, 13.f, fmaf(q3.y, 14.f, fmaf(q3.z, 15.f, q3.w * 16.f)));
        float a4 = fmaf(q4.x, 17.f, fmaf(q4.y, 18.f, fmaf(q4.z, 19.f, q4.w * 20.f)));
        float fa = ((a0 + a1) + (a2 + a3)) + a4;
        int v = (int)fa;                  // exact: small ints
        sav[l] = (v == 0) ? 20 : v - 1;
        if (v != 0) lmax = l;             // r ascending -> last valid wins
    }
    lmax = __reduce_max_sync(0xFFFFFFFFu, lmax);
    if (lane == 0) sWmax[warp] = lmax;
    __syncthreads();

    int Lmax = max(max(sWmax[0], sWmax[1]), max(sWmax[2], sWmax[3]));
    int NB = min(L_DIM, (Lmax + 4 + 31) & ~31);   // positions >= NB contribute 0

    // --- Phase B: exclusive class masks, packed ---
    for (int l = tid; l < NB; l += TPB) {
        unsigned c1, c2, c3;
        if (l == 0) {
            c3 = (1u << sav[0]) | (1u << sav[1]) | (1u << sav[2]) | (1u << sav[3]);
            c2 = 0u; c1 = 0u;
        } else if (l == L_DIM - 1) {
            c3 = (1u << sav[511]) | (1u << sav[510]) | (1u << sav[509]) | (1u << sav[508]);
            c2 = 0u; c1 = 0u;
        } else {
            unsigned m1 = (1u << sav[l - 1]) | (1u << sav[l + 1]);
            unsigned m2 = ((l >= 2) ? (1u << sav[l - 2]) : 0u) |
                          ((l <= 509) ? (1u << sav[l + 2]) : 0u);
            unsigned m3 = ((l >= 3) ? (1u << sav[l - 3]) : 0u) |
                          ((l <= 508) ? (1u << sav[l + 3]) : 0u);
            c3 = m3;
            c2 = m2 & ~m3;
            c1 = m1 & ~(m2 | m3);
        }
        scm[l]  = ((unsigned long long)c2 << 32) | c3;
        sc1s[l] = (c1 & 0x1FFFFFu) | ((unsigned)sav[l] << 24);
    }
    __syncthreads();

    float s0 = stdv[0];
    float inv = 1.f / (2.f * s0 * s0);
    float v1 = expf(-1.f * inv), v2 = expf(-4.f * inv), v3 = expf(-9.f * inv);

    int abase = warp * 5;
    unsigned long long acc[5][4];
    #pragma unroll
    for (int aa = 0; aa < 5; aa++)
        #pragma unroll
        for (int j = 0; j < 4; j++) acc[aa][j] = 0ull;

    unsigned abit[5]; int vb[5];
    #pragma unroll
    for (int aa = 0; aa < 5; aa++) {
        abit[aa] = 1u << (abase + aa);
        vb[aa] = (abase + aa) * 21;
    }

    // --- Phase C: bounded, barrier-free packed accumulation ---
    int NI = NB >> 5;
    #pragma unroll 2
    for (int i = 0; i < NI; i++) {
        int l = lane + 32 * i;
        unsigned long long m = scm[l];
        unsigned c3m = (unsigned)m;
        unsigned c2m = (unsigned)(m >> 32);
        unsigned t = sc1s[l];
        unsigned c1m = t & 0x1FFFFFu;
        int s = (int)(t >> 24);
        unsigned long long w0p = Wp[l];
        unsigned long long w1p = Wp[512 + l];
        unsigned long long w2p = Wp[1024 + l];
        unsigned long long w3p = Wp[1536 + l];
        #pragma unroll
        for (int aa = 0; aa < 5; aa++) {
            float rv = (c3m & abit[aa]) ? v3
                     : (c2m & abit[aa]) ? v2
                     : (c1m & abit[aa]) ? v1 : 0.f;
            float h = rv + Vt[vb[aa] + s];
            unsigned long long hh = pack2(h, h);
            ffma2(acc[aa][0], w0p, hh);
            ffma2(acc[aa][1], w1p, hh);
            ffma2(acc[aa][2], w2p, hh);
            ffma2(acc[aa][3], w3p, hh);
        }
    }

    // --- Phase D: f32x2 butterfly reduction + stores ---
    #pragma unroll
    for (int aa = 0; aa < 5; aa++) {
        #pragma unroll
        for (int j = 0; j < 4; j++) {
            unsigned long long v = acc[aa][j];
            #pragma unroll
            for (int off = 16; off; off >>= 1)
                v = add2(v, shfl64(v, off));
            acc[aa][j] = v;
        }
        if (lane == 0) {
            float r[8];
            #pragma unroll
            for (int j = 0; j < 4; j++) unpack2(acc[aa][j], r[2 * j], r[2 * j + 1]);
            float4* o = (float4*)(out + (size_t)b * (A_DIM * CH) + (abase + aa) * CH);
            o[0] = make_float4(r[0], r[1], r[2], r[3]);
            o[1] = make_float4(r[4], r[5], r[6], r[7]);
        }
    }
}

// ---------------------------------------------------------------------------
// Inputs (metadata order): x, masks(unused), lpm, pm, std, w0, ws
// Output: float32 (B, A, CH) = (1024, 20, 8)
// ---------------------------------------------------------------------------
extern "C" void kernel_launch(void* const* d_in, const int* in_sizes, int n_in,
                              void* d_out, int out_size) {
    const float* x    = (const float*)d_in[0];
    const float* lpm  = (const float*)d_in[2];
    const float* pm   = (const float*)d_in[3];
    const float* stdv = (const float*)d_in[4];
    const float* w0   = (const float*)d_in[5];
    const float* ws   = (const float*)d_in[6];
    float* out = (float*)d_out;

    build_w_bwd<<<CH, 256>>>(w0, ws);
    main_kernel<<<B_DIM, TPB>>>(x, lpm, pm, stdv, out);
}

// round 8
// speedup vs baseline: 1.1594x; 1.0881x over previous
#include <cuda_runtime.h>
#include <math.h>

#define A_DIM 20
#define L_DIM 512
#define CH 8
#define B_DIM 1024
#define TPB 128   // 4 warps; warp w owns amino acids 5w..5w+4

__device__ float g_Wf[4 * L_DIM * 2];  // interleaved channel pairs: [j*1024 + 2l + parity]
__device__ float g_Vt[A_DIM * 21];     // Vt[a*21+s] = V[s][a] + (s==a); s=20 -> 0
__device__ float g_vk[3];              // v1, v2, v3

// ---------------------------------------------------------------------------
// f32x2 packed helpers
// ---------------------------------------------------------------------------
__device__ __forceinline__ unsigned long long pack2(float lo, float hi) {
    unsigned long long r;
    asm("mov.b64 %0, {%1, %2};" : "=l"(r) : "f"(lo), "f"(hi));
    return r;
}
__device__ __forceinline__ void unpack2(unsigned long long v, float& lo, float& hi) {
    asm("mov.b64 {%0, %1}, %2;" : "=f"(lo), "=f"(hi) : "l"(v));
}
__device__ __forceinline__ void ffma2(unsigned long long& d, unsigned long long a,
                                      unsigned long long b) {
    asm("fma.rn.f32x2 %0, %1, %2, %0;" : "+l"(d) : "l"(a), "l"(b));
}
__device__ __forceinline__ unsigned long long add2(unsigned long long a,
                                                   unsigned long long b) {
    unsigned long long r;
    asm("add.rn.f32x2 %0, %1, %2;" : "=l"(r) : "l"(a), "l"(b));
    return r;
}

// ---------------------------------------------------------------------------
// Kernel 1: W via adjoint composition (one block per output channel) +
// block 0 additionally materializes g_Vt / g_vk (block-invariant tables).
// ---------------------------------------------------------------------------
__global__ __launch_bounds__(256) void build_w_bwd(const float* __restrict__ w0,
                                                   const float* __restrict__ ws,
                                                   const float* __restrict__ lpm,
                                                   const float* __restrict__ pm,
                                                   const float* __restrict__ stdv) {
    __shared__ float GA[CH][256];
    __shared__ float GB[CH][256];
    __shared__ float sws[8 * CH * CH * 3];
    __shared__ float sw0[CH * 3];
    int tid = threadIdx.x, oc = blockIdx.x;

    if (oc == 0) {
        for (int i = tid; i < A_DIM * 21; i += 256) {
            int a = i / 21, s = i % 21;
            float v = (s == a) ? 1.f : 0.f;
            if (s < A_DIM) {
                if (a > s && a <= A_DIM - 2)
                    v += fminf(fmaxf(lpm[s * A_DIM + a], 0.001f), 1.f) * pm[s * A_DIM + a];
                if (a < s)
                    v += fminf(fmaxf(lpm[a * A_DIM + s], 0.001f), 1.f) * pm[a * A_DIM + s];
            }
            g_Vt[i] = v;
        }
        if (tid < 3) {
            float s0 = stdv[0];
            float k = (float)(tid + 1);
            g_vk[tid] = expf(-(k * k) / (2.f * s0 * s0));
        }
    }

    for (int i = tid; i < 8 * CH * CH * 3; i += 256) sws[i] = ws[i];
    if (tid < CH * 3) sw0[tid] = w0[tid];
    if (tid < CH) GA[tid][0] = (tid == oc) ? 1.f : 0.f;
    __syncthreads();

    float (*cur)[256] = GA, (*nxt)[256] = GB;
    for (int j = 7; j >= 0; j--) {
        int L2h = 256 >> j;
        const float* w = &sws[j * CH * CH * 3];
        for (int e = tid; e < CH * L2h; e += 256) {
            int ci = e / L2h, q = e % L2h;
            float acc = 0.f;
            #pragma unroll
            for (int co = 0; co < CH; co++) {
                const float* wc = w + (co * CH + ci) * 3;
                #pragma unroll
                for (int t = 0; t < 3; t++) {
                    int p = q + 1 - t;
                    if (p >= 0 && p < L2h) acc += wc[t] * 0.5f * cur[co][p >> 1];
                }
            }
            nxt[ci][q] = acc;
        }
        __syncthreads();
        float (*tmp)[256] = cur; cur = nxt; nxt = tmp;
    }
    // final: write interleaved pair layout
    float* gw = g_Wf + (oc >> 1) * (L_DIM * 2) + (oc & 1);
    for (int q = tid; q < 512; q += 256) {
        float acc = 0.f;
        #pragma unroll
        for (int co = 0; co < CH; co++) {
            #pragma unroll
            for (int t = 0; t < 3; t++) {
                int p = q + 1 - t;
                if (p >= 0 && p < 512) acc += sw0[co * 3 + t] * 0.5f * cur[co][p >> 1];
            }
        }
        gw[2 * q] = acc;
    }
}

// ---------------------------------------------------------------------------
// Kernel 2: main. One block per batch element.
// ---------------------------------------------------------------------------
__global__ __launch_bounds__(TPB) void main_kernel(const float* __restrict__ x,
                                                   float* __restrict__ out) {
    __shared__ unsigned long long Wp[4 * L_DIM];   // channel pairs [j*512+l]
    __shared__ float Vt[A_DIM * 21];
    __shared__ unsigned long long scm[L_DIM];      // (c2 << 32) | c3
    __shared__ unsigned sc1s[L_DIM];               // c1 | (s << 24)
    __shared__ int sav[L_DIM];
    __shared__ int sWmax[4];

    int tid = threadIdx.x, b = blockIdx.x;
    int warp = tid >> 5, lane = tid & 31;

    // --- Phase A first: decode one-hot (LDG burst overlaps copies below) ---
    const float* xb = x + (size_t)b * (L_DIM * A_DIM);
    int lmax = -1;
    #pragma unroll
    for (int r = 0; r < 4; r++) {
        int l = tid + r * TPB;
        const float4* p = (const float4*)(xb + l * A_DIM);
        float4 q0 = p[0], q1 = p[1], q2 = p[2], q3 = p[3], q4 = p[4];
        float a0 = fmaf(q0.x, 1.f, fmaf(q0.y, 2.f, fmaf(q0.z, 3.f, q0.w * 4.f)));
        float a1 = fmaf(q1.x, 5.f, fmaf(q1.y, 6.f, fmaf(q1.z, 7.f, q1.w * 8.f)));
        float a2 = fmaf(q2.x, 9.f, fmaf(q2.y, 10.f, fmaf(q2.z, 11.f, q2.w * 12.f)));
        float a3 = fmaf(q3.x, 13.f, fmaf(q3.y, 14.f, fmaf(q3.z, 15.f, q3.w * 16.f)));
        float a4 = fmaf(q4.x, 17.f, fmaf(q4.y, 18.f, fmaf(q4.z, 19.f, q4.w * 20.f)));
        float fa = ((a0 + a1) + (a2 + a3)) + a4;
        int v = (int)fa;                  // exact: small ints
        sav[l] = (v == 0) ? 20 : v - 1;
        if (v != 0) lmax = l;
    }

    // --- block-invariant tables: straight vector copies ---
    {
        const float4* srcW = (const float4*)g_Wf;
        float4* dstW = (float4*)Wp;
        #pragma unroll
        for (int r = 0; r < 8; r++) dstW[tid + r * TPB] = srcW[tid + r * TPB];
        const float4* srcV = (const float4*)g_Vt;   // 420 floats = 105 float4
        float4* dstV = (float4*)Vt;
        if (tid < 105) dstV[tid] = srcV[tid];
    }
    float v1 = g_vk[0], v2 = g_vk[1], v3 = g_vk[2];

    lmax = __reduce_max_sync(0xFFFFFFFFu, lmax);
    if (lane == 0) sWmax[warp] = lmax;
    __syncthreads();

    int Lmax = max(max(sWmax[0], sWmax[1]), max(sWmax[2], sWmax[3]));
    int NB = min(L_DIM, (Lmax + 4 + 31) & ~31);   // positions >= NB contribute 0

    // --- Phase B: exclusive class masks, packed ---
    for (int l = tid; l < NB; l += TPB) {
        unsigned c1, c2, c3;
        if (l == 0) {
            c3 = (1u << sav[0]) | (1u << sav[1]) | (1u << sav[2]) | (1u << sav[3]);
            c2 = 0u; c1 = 0u;
        } else if (l == L_DIM - 1) {
            c3 = (1u << sav[511]) | (1u << sav[510]) | (1u << sav[509]) | (1u << sav[508]);
            c2 = 0u; c1 = 0u;
        } else {
            unsigned m1 = (1u << sav[l - 1]) | (1u << sav[l + 1]);
            unsigned m2 = ((l >= 2) ? (1u << sav[l - 2]) : 0u) |
                          ((l <= 509) ? (1u << sav[l + 2]) : 0u);
            unsigned m3 = ((l >= 3) ? (1u << sav[l - 3]) : 0u) |
                          ((l <= 508) ? (1u << sav[l + 3]) : 0u);
            c3 = m3;
            c2 = m2 & ~m3;
            c1 = m1 & ~(m2 | m3);
        }
        scm[l]  = ((unsigned long long)c2 << 32) | c3;
        sc1s[l] = (c1 & 0x1FFFFFu) | ((unsigned)sav[l] << 24);
    }
    __syncthreads();

    int abase = warp * 5;
    unsigned long long acc[5][4];
    #pragma unroll
    for (int aa = 0; aa < 5; aa++)
        #pragma unroll
        for (int j = 0; j < 4; j++) acc[aa][j] = 0ull;

    unsigned abit[5]; int vb[5];
    #pragma unroll
    for (int aa = 0; aa < 5; aa++) {
        abit[aa] = 1u << (abase + aa);
        vb[aa] = (abase + aa) * 21;
    }

    // --- Phase C: bounded, barrier-free packed accumulation ---
    int NI = NB >> 5;
    #pragma unroll 2
    for (int i = 0; i < NI; i++) {
        int l = lane + 32 * i;
        unsigned long long m = scm[l];
        unsigned c3m = (unsigned)m;
        unsigned c2m = (unsigned)(m >> 32);
        unsigned t = sc1s[l];
        unsigned c1m = t & 0x1FFFFFu;
        int s = (int)(t >> 24);
        unsigned long long w0p = Wp[l];
        unsigned long long w1p = Wp[512 + l];
        unsigned long long w2p = Wp[1024 + l];
        unsigned long long w3p = Wp[1536 + l];
        #pragma unroll
        for (int aa = 0; aa < 5; aa++) {
            float rv = (c3m & abit[aa]) ? v3
                     : (c2m & abit[aa]) ? v2
                     : (c1m & abit[aa]) ? v1 : 0.f;
            float h = rv + Vt[vb[aa] + s];
            unsigned long long hh = pack2(h, h);
            ffma2(acc[aa][0], w0p, hh);
            ffma2(acc[aa][1], w1p, hh);
            ffma2(acc[aa][2], w2p, hh);
            ffma2(acc[aa][3], w3p, hh);
        }
    }

    // --- Phase D: native u64 butterfly (2 SHFL + 1 FADD2 per step) ---
    #pragma unroll
    for (int aa = 0; aa < 5; aa++) {
        #pragma unroll
        for (int j = 0; j < 4; j++) {
            unsigned long long v = acc[aa][j];
            #pragma unroll
            for (int off = 16; off; off >>= 1)
                v = add2(v, __shfl_xor_sync(0xFFFFFFFFu, v, off));
            acc[aa][j] = v;
        }
        if (lane == 0) {
            float r[8];
            #pragma unroll
            for (int j = 0; j < 4; j++) unpack2(acc[aa][j], r[2 * j], r[2 * j + 1]);
            float4* o = (float4*)(out + (size_t)b * (A_DIM * CH) + (abase + aa) * CH);
            o[0] = make_float4(r[0], r[1], r[2], r[3]);
            o[1] = make_float4(r[4], r[5], r[6], r[7]);
        }
    }
}

// ---------------------------------------------------------------------------
// Inputs (metadata order): x, masks(unused), lpm, pm, std, w0, ws
// Output: float32 (B, A, CH) = (1024, 20, 8)
// ---------------------------------------------------------------------------
extern "C" void kernel_launch(void* const* d_in, const int* in_sizes, int n_in,
                              void* d_out, int out_size) {
    const float* x    = (const float*)d_in[0];
    const float* lpm  = (const float*)d_in[2];
    const float* pm   = (const float*)d_in[3];
    const float* stdv = (const float*)d_in[4];
    const float* w0   = (const float*)d_in[5];
    const float* ws   = (const float*)d_in[6];
    float* out = (float*)d_out;

    build_w_bwd<<<CH, 256>>>(w0, ws, lpm, pm, stdv);
    main_kernel<<<B_DIM, TPB>>>(x, out);
}

// round 9
// speedup vs baseline: 1.2150x; 1.0479x over previous
#include <cuda_runtime.h>
#include <math.h>

#define A_DIM 20
#define L_DIM 512
#define CH 8
#define B_DIM 1024
#define TPB 128   // 4 warps; warp w owns amino acids 5w..5w+4

__device__ float g_Wf[4 * L_DIM * 2];  // interleaved channel pairs: [j*1024 + 2l + parity]
__device__ float g_Vt[A_DIM * 21];     // Vt[a*21+s] = V[s][a] + (s==a); s=20 -> 0
__device__ float g_vk[3];              // v1, v2, v3
__device__ int   g_flag;               // monotonic build-done counter (zero-init once)

// ---------------------------------------------------------------------------
// f32x2 packed helpers
// ---------------------------------------------------------------------------
__device__ __forceinline__ unsigned long long pack2(float lo, float hi) {
    unsigned long long r;
    asm("mov.b64 %0, {%1, %2};" : "=l"(r) : "f"(lo), "f"(hi));
    return r;
}
__device__ __forceinline__ void unpack2(unsigned long long v, float& lo, float& hi) {
    asm("mov.b64 {%0, %1}, %2;" : "=f"(lo), "=f"(hi) : "l"(v));
}
__device__ __forceinline__ void ffma2(unsigned long long& d, unsigned long long a,
                                      unsigned long long b) {
    asm("fma.rn.f32x2 %0, %1, %2, %0;" : "+l"(d) : "l"(a), "l"(b));
}
__device__ __forceinline__ unsigned long long add2(unsigned long long a,
                                                   unsigned long long b) {
    unsigned long long r;
    asm("add.rn.f32x2 %0, %1, %2;" : "=l"(r) : "l"(a), "l"(b));
    return r;
}

// ---------------------------------------------------------------------------
// Fused kernel. One block per batch element.
// Blocks 0..7 additionally build W channel oc=blockIdx (block 0 also Vt/vk).
// smem overlay: build buffers reuse the Wp/scm/sc1s region (disjoint in time).
// ---------------------------------------------------------------------------
__global__ __launch_bounds__(TPB) void fused_kernel(const float* __restrict__ x,
                                                    const float* __restrict__ lpm,
                                                    const float* __restrict__ pm,
                                                    const float* __restrict__ stdv,
                                                    const float* __restrict__ w0,
                                                    const float* __restrict__ ws,
                                                    float* __restrict__ out) {
    __shared__ __align__(16) unsigned char ov[22528];
    __shared__ float Vt[A_DIM * 21];
    __shared__ int   sav[L_DIM];
    __shared__ int   sWmax[4];
    __shared__ float sw0s[CH * 3];

    // main-phase views of the overlay
    unsigned long long* Wp   = (unsigned long long*)ov;             // 16 KB [j*512+l]
    unsigned long long* scm  = (unsigned long long*)(ov + 16384);   // 4 KB  (c2<<32)|c3
    unsigned*           sc1s = (unsigned*)(ov + 20480);             // 2 KB  c1 | (s<<24)

    int tid = threadIdx.x, b = blockIdx.x;
    int warp = tid >> 5, lane = tid & 31;

    // --- Phase A: decode one-hot via weighted-sum FMA (LDG burst first) ---
    const float* xb = x + (size_t)b * (L_DIM * A_DIM);
    int lmax = -1;
    #pragma unroll
    for (int r = 0; r < 4; r++) {
        int l = tid + r * TPB;
        const float4* p = (const float4*)(xb + l * A_DIM);
        float4 q0 = p[0], q1 = p[1], q2 = p[2], q3 = p[3], q4 = p[4];
        float a0 = fmaf(q0.x, 1.f, fmaf(q0.y, 2.f, fmaf(q0.z, 3.f, q0.w * 4.f)));
        float a1 = fmaf(q1.x, 5.f, fmaf(q1.y, 6.f, fmaf(q1.z, 7.f, q1.w * 8.f)));
        float a2 = fmaf(q2.x, 9.f, fmaf(q2.y, 10.f, fmaf(q2.z, 11.f, q2.w * 12.f)));
        float a3 = fmaf(q3.x, 13.f, fmaf(q3.y, 14.f, fmaf(q3.z, 15.f, q3.w * 16.f)));
        float a4 = fmaf(q4.x, 17.f, fmaf(q4.y, 18.f, fmaf(q4.z, 19.f, q4.w * 20.f)));
        float fa = ((a0 + a1) + (a2 + a3)) + a4;
        int v = (int)fa;                  // exact: small ints
        sav[l] = (v == 0) ? 20 : v - 1;
        if (v != 0) lmax = l;
    }
    lmax = __reduce_max_sync(0xFFFFFFFFu, lmax);
    if (lane == 0) sWmax[warp] = lmax;

    // --- W builder (blocks 0..7): adjoint composition into g_Wf ---
    if (b < CH) {
        if (b == 0) {
            for (int i = tid; i < A_DIM * 21; i += TPB) {
                int a = i / 21, s = i % 21;
                float v = (s == a) ? 1.f : 0.f;
                if (s < A_DIM) {
                    if (a > s && a <= A_DIM - 2)
                        v += fminf(fmaxf(lpm[s * A_DIM + a], 0.001f), 1.f) * pm[s * A_DIM + a];
                    if (a < s)
                        v += fminf(fmaxf(lpm[a * A_DIM + s], 0.001f), 1.f) * pm[a * A_DIM + s];
                }
                g_Vt[i] = v;
            }
            if (tid < 3) {
                float s0 = stdv[0];
                float k = (float)(tid + 1);
                g_vk[tid] = expf(-(k * k) / (2.f * s0 * s0));
            }
        }
        // overlay build views (free until Wp/scm/sc1s are used)
        float* buf0 = (float*)ov;             // stride 256, 8 KB
        float* buf1 = (float*)(ov + 8192);    // stride 128, 4 KB
        float* sws  = (float*)(ov + 12288);   // 1536 floats, 6 KB

        for (int i = tid; i < 8 * CH * CH * 3; i += TPB) sws[i] = ws[i];
        if (tid < CH * 3) sw0s[tid] = w0[tid];
        if (tid < CH) buf0[tid * 256] = (tid == b) ? 1.f : 0.f;
        __syncthreads();

        float* cur = buf0; int curs = 256;
        for (int j = 7; j >= 0; j--) {
            int sh = 8 - j;                    // L2h = 1 << sh
            int L2h = 1 << sh;
            float* dst = (j & 1) ? buf1 : buf0;
            int dsts = (j & 1) ? 128 : 256;
            const float* w = sws + j * (CH * CH * 3);
            for (int e = tid; e < CH * L2h; e += TPB) {
                int ci = e >> sh, q = e & (L2h - 1);
                float acc = 0.f;
                #pragma unroll
                for (int co = 0; co < CH; co++) {
                    const float* wc = w + (co * CH + ci) * 3;
                    #pragma unroll
                    for (int t = 0; t < 3; t++) {
                        int p = q + 1 - t;
                        if (p >= 0 && p < L2h) acc += wc[t] * 0.5f * cur[co * curs + (p >> 1)];
                    }
                }
                dst[ci * dsts + q] = acc;
            }
            __syncthreads();
            cur = dst; curs = dsts;
        }
        // final backward through pool0+conv0: cur = buf0 (CH x 256)
        float* gw = g_Wf + (b >> 1) * (L_DIM * 2) + (b & 1);
        for (int q = tid; q < 512; q += TPB) {
            float acc = 0.f;
            #pragma unroll
            for (int co = 0; co < CH; co++) {
                #pragma unroll
                for (int t = 0; t < 3; t++) {
                    int p = q + 1 - t;
                    if (p >= 0 && p < 512) acc += sw0s[co * 3 + t] * 0.5f * cur[co * 256 + (p >> 1)];
                }
            }
            gw[2 * q] = acc;
        }
        __threadfence();
        __syncthreads();
        if (tid == 0) atomicAdd(&g_flag, 1);
    }
    __syncthreads();   // sav/sWmax ready for everyone; builders done with overlay

    int Lmax = max(max(sWmax[0], sWmax[1]), max(sWmax[2], sWmax[3]));
    int NB = min(L_DIM, (Lmax + 4 + 31) & ~31);   // positions >= NB contribute 0

    // --- Phase B: exclusive class masks (independent of W -> before spin) ---
    for (int l = tid; l < NB; l += TPB) {
        unsigned c1, c2, c3;
        if (l == 0) {
            c3 = (1u << sav[0]) | (1u << sav[1]) | (1u << sav[2]) | (1u << sav[3]);
            c2 = 0u; c1 = 0u;
        } else if (l == L_DIM - 1) {
            c3 = (1u << sav[511]) | (1u << sav[510]) | (1u << sav[509]) | (1u << sav[508]);
            c2 = 0u; c1 = 0u;
        } else {
            unsigned m1 = (1u << sav[l - 1]) | (1u << sav[l + 1]);
            unsigned m2 = ((l >= 2) ? (1u << sav[l - 2]) : 0u) |
                          ((l <= 509) ? (1u << sav[l + 2]) : 0u);
            unsigned m3 = ((l >= 3) ? (1u << sav[l - 3]) : 0u) |
                          ((l <= 508) ? (1u << sav[l + 3]) : 0u);
            c3 = m3;
            c2 = m2 & ~m3;
            c1 = m1 & ~(m2 | m3);
        }
        scm[l]  = ((unsigned long long)c2 << 32) | c3;
        sc1s[l] = (c1 & 0x1FFFFFu) | ((unsigned)sav[l] << 24);
    }

    // --- rendezvous: wait until all 8 W channels (+Vt/vk) are published ---
    if (tid == 0) {
        while (atomicAdd(&g_flag, 0) < CH) __nanosleep(64);
    }
    __syncthreads();
    __threadfence();   // acquire: order subsequent g_Wf/g_Vt reads

    // --- copy block-invariant tables (straight vector copies) ---
    {
        const float4* srcW = (const float4*)g_Wf;
        float4* dstW = (float4*)Wp;
        #pragma unroll
        for (int r = 0; r < 8; r++) dstW[tid + r * TPB] = srcW[tid + r * TPB];
        const float4* srcV = (const float4*)g_Vt;   // 420 floats = 105 float4
        float4* dstV = (float4*)Vt;
        if (tid < 105) dstV[tid] = srcV[tid];
    }
    float v1 = g_vk[0], v2 = g_vk[1], v3 = g_vk[2];
    __syncthreads();

    int abase = warp * 5;
    unsigned long long acc[5][4];
    #pragma unroll
    for (int aa = 0; aa < 5; aa++)
        #pragma unroll
        for (int j = 0; j < 4; j++) acc[aa][j] = 0ull;

    unsigned abit[5]; int vb[5];
    #pragma unroll
    for (int aa = 0; aa < 5; aa++) {
        abit[aa] = 1u << (abase + aa);
        vb[aa] = (abase + aa) * 21;
    }

    // --- Phase C: bounded, barrier-free packed accumulation ---
    int NI = NB >> 5;
    #pragma unroll 2
    for (int i = 0; i < NI; i++) {
        int l = lane + 32 * i;
        unsigned long long m = scm[l];
        unsigned c3m = (unsigned)m;
        unsigned c2m = (unsigned)(m >> 32);
        unsigned t = sc1s[l];
        unsigned c1m = t & 0x1FFFFFu;
        int s = (int)(t >> 24);
        unsigned long long w0p = Wp[l];
        unsigned long long w1p = Wp[512 + l];
        unsigned long long w2p = Wp[1024 + l];
        unsigned long long w3p = Wp[1536 + l];
        #pragma unroll
        for (int aa = 0; aa < 5; aa++) {
            float rv = (c3m & abit[aa]) ? v3
                     : (c2m & abit[aa]) ? v2
                     : (c1m & abit[aa]) ? v1 : 0.f;
            float h = rv + Vt[vb[aa] + s];
            unsigned long long hh = pack2(h, h);
            ffma2(acc[aa][0], w0p, hh);
            ffma2(acc[aa][1], w1p, hh);
            ffma2(acc[aa][2], w2p, hh);
            ffma2(acc[aa][3], w3p, hh);
        }
    }

    // --- Phase D: native u64 butterfly (2 SHFL + 1 FADD2 per step) ---
    #pragma unroll
    for (int aa = 0; aa < 5; aa++) {
        #pragma unroll
        for (int j = 0; j < 4; j++) {
            unsigned long long v = acc[aa][j];
            #pragma unroll
            for (int off = 16; off; off >>= 1)
                v = add2(v, __shfl_xor_sync(0xFFFFFFFFu, v, off));
            acc[aa][j] = v;
        }
        if (lane == 0) {
            float r[8];
            #pragma unroll
            for (int j = 0; j < 4; j++) unpack2(acc[aa][j], r[2 * j], r[2 * j + 1]);
            float4* o = (float4*)(out + (size_t)b * (A_DIM * CH) + (abase + aa) * CH);
            o[0] = make_float4(r[0], r[1], r[2], r[3]);
            o[1] = make_float4(r[4], r[5], r[6], r[7]);
        }
    }
}

// ---------------------------------------------------------------------------
// Inputs (metadata order): x, masks(unused), lpm, pm, std, w0, ws
// Output: float32 (B, A, CH) = (1024, 20, 8)
// ---------------------------------------------------------------------------
extern "C" void kernel_launch(void* const* d_in, const int* in_sizes, int n_in,
                              void* d_out, int out_size) {
    const float* x    = (const float*)d_in[0];
    const float* lpm  = (const float*)d_in[2];
    const float* pm   = (const float*)d_in[3];
    const float* stdv = (const float*)d_in[4];
    const float* w0   = (const float*)d_in[5];
    const float* ws   = (const float*)d_in[6];
    float* out = (float*)d_out;

    fused_kernel<<<B_DIM, TPB>>>(x, lpm, pm, stdv, w0, ws, out);
}